// round 16
// baseline (speedup 1.0000x reference)
#include <cuda_runtime.h>
#include <cuda_bf16.h>
#include <cstdint>
#include <cstddef>

#define NB 32
#define NN 1024
#define NF 64
#define NO 128

typedef unsigned long long u64;
typedef uint32_t u32;

#define KC (-14.4269504089f)                 // -10 * log2(e)
#define INV_KC (-0.0693147181f)              // 1 / KC

// Device scratch: coefficients from pairwise stage
__device__ float c1v_g[NB * NN];
__device__ float c2v_g[NB * NN];

__device__ __forceinline__ u32 smem_u32(const void* p) {
    u32 a;
    asm("{ .reg .u64 t; cvta.to.shared.u64 t, %1; cvt.u32.u64 %0, t; }" : "=r"(a) : "l"(p));
    return a;
}
__device__ __forceinline__ float fast_exp2(float t) {
    float r; asm("ex2.approx.f32 %0, %1;" : "=f"(r) : "f"(t)); return r;
}
__device__ __forceinline__ u64 pk2f(float lo, float hi) {
    u64 r; asm("mov.b64 %0, {%1, %2};" : "=l"(r) : "f"(lo), "f"(hi)); return r;
}
__device__ __forceinline__ void up2f(u64 v, float& a, float& b) {
    asm("mov.b64 {%0, %1}, %2;" : "=f"(a), "=f"(b) : "l"(v));
}
#define ADD2(d, a, b)   asm("add.rn.f32x2 %0, %1, %2;" : "=l"(d) : "l"(a), "l"(b))
#define FMA2IO(d, a, b) asm("fma.rn.f32x2 %0, %1, %2, %0;" : "+l"(d) : "l"(a), "l"(b))
#define ADD2ACC(d, a)   asm("add.rn.f32x2 %0, %1, %0;" : "+l"(d) : "l"(a))

#define LDSM_X4(r0, r1, r2, r3, addr) \
    asm volatile("ldmatrix.sync.aligned.m8n8.x4.shared.b16 {%0,%1,%2,%3}, [%4];" \
                 : "=r"(r0), "=r"(r1), "=r"(r2), "=r"(r3) : "r"(addr))

__device__ __forceinline__ void mma16816(float* d, const u32* a, const u32* b) {
    asm volatile(
        "mma.sync.aligned.m16n8k16.row.col.f32.bf16.bf16.f32 "
        "{%0,%1,%2,%3}, {%4,%5,%6,%7}, {%8,%9}, {%0,%1,%2,%3};"
        : "+f"(d[0]), "+f"(d[1]), "+f"(d[2]), "+f"(d[3])
        : "r"(a[0]), "r"(a[1]), "r"(a[2]), "r"(a[3]), "r"(b[0]), "r"(b[1]));
}

// ---------------------------------------------------------------------------
// Kernel 1: pairwise coefficients. grid = 256 (8/batch), 512 threads.
// 128 j's per CTA; q = t>>7 warp-uniform (broadcast smem loads), jl = t&127.
// Ends with PDL trigger so the gemm epilogue can proceed.
// ---------------------------------------------------------------------------
__global__ void __launch_bounds__(512) coef_kernel(
    const float* __restrict__ x, const float* __restrict__ mask)
{
    __shared__ __align__(16) float xs[NN];
    __shared__ __align__(16) float ys[NN];
    __shared__ __align__(16) float kz[NN];
    __shared__ float redw[4][128];
    __shared__ float redd[4][128];

    const int b = blockIdx.x >> 3;
    const int jbase = (blockIdx.x & 7) * 128;
    const int t = threadIdx.x;

    for (int i = t; i < NN; i += 512) {
        float2 c = *(const float2*)(x + ((size_t)b * NN + i) * NF + (NF - 2));
        xs[i] = c.x;
        ys[i] = c.y;
        kz[i] = KC * fmaf(c.y, c.y, c.x * c.x);
    }
    __syncthreads();

    const int q  = t >> 7;        // i-quarter, uniform within each warp
    const int jl = t & 127;
    const int j  = jbase + jl;
    const float Km2jx = -2.0f * KC * xs[j];
    const float Km2jy = -2.0f * KC * ys[j];
    const float Krj = kz[j];

    const u64 Kx2 = pk2f(Km2jx, Km2jx);
    const u64 Ky2 = pk2f(Km2jy, Km2jy);
    const u64 Kr2 = pk2f(Krj, Krj);

    const ulonglong2* X2 = (const ulonglong2*)(xs) + q * 64;
    const ulonglong2* Y2 = (const ulonglong2*)(ys) + q * 64;
    const ulonglong2* Z2 = (const ulonglong2*)(kz) + q * 64;

    u64 S1A = 0ULL, S2A = 0ULL, S1B = 0ULL, S2B = 0ULL;
    #pragma unroll 4
    for (int i = 0; i < 64; i++) {          // 4 points per iteration, broadcast loads
        ulonglong2 X = X2[i];
        ulonglong2 Y = Y2[i];
        ulonglong2 Z = Z2[i];

        u64 u0; ADD2(u0, Z.x, Kr2);
        FMA2IO(u0, Y.x, Ky2);
        FMA2IO(u0, X.x, Kx2);
        float ua, ub; up2f(u0, ua, ub);
        u64 e0 = pk2f(fast_exp2(ua), fast_exp2(ub));
        ADD2ACC(S1A, e0);
        FMA2IO(S2A, u0, e0);

        u64 u1; ADD2(u1, Z.y, Kr2);
        FMA2IO(u1, Y.y, Ky2);
        FMA2IO(u1, X.y, Kx2);
        float uc, ud; up2f(u1, uc, ud);
        u64 e1 = pk2f(fast_exp2(uc), fast_exp2(ud));
        ADD2ACC(S1B, e1);
        FMA2IO(S2B, u1, e1);
    }

    float a, bb, c, d;
    up2f(S1A, a, bb); up2f(S1B, c, d);
    float s1 = (a + bb) + (c + d);
    up2f(S2A, a, bb); up2f(S2B, c, d);
    float s2 = (a + bb) + (c + d);

    redw[q][jl] = s1;
    redd[q][jl] = s2;
    __syncthreads();

    if (t < 128) {
        float ws = (redw[0][t] + redw[1][t]) + (redw[2][t] + redw[3][t]);
        float dw = (redd[0][t] + redd[1][t]) + (redd[2][t] + redd[3][t]);
        int gj = b * NN + jbase + t;
        float m = mask[gj];
        c1v_g[gj] = fmaf(ws, m, -1.0f);
        c2v_g[gj] = (dw * INV_KC) * m;
    }
    __threadfence();
    __syncthreads();
    cudaTriggerProgrammaticLaunchCompletion();
}

// ---------------------------------------------------------------------------
// Kernel 2: GEMM, pair-interleaved B (K=64, N=256).
//   B[2c+s][k] = A[s*64+k][c]  ->  thread's mma col pair = (G0[c], G1[c]).
//   Mainloop has NO dependency on coef; cudaGridDependencySynchronize()
//   gates only the epilogue:  out = (G0 + c1*G1 + c2*A2 + bias) * m.
// grid = 256 (2 x 64-row tiles), 256 threads (8 warps), warp 32r x 64 B-rows.
// smem 92.2KB -> 2 CTAs/SM; co-residency with coef during overlap.
// ---------------------------------------------------------------------------
#define XROW 144
#define OFF_XHI 0
#define OFF_XLO (64 * XROW)                  // 9216
#define OFF_BHI (2 * 64 * XROW)              // 18432
#define OFF_BLO (OFF_BHI + 256 * XROW)       // 55296
#define GSMEM_TOTAL (OFF_BLO + 256 * XROW)   // 92160

__global__ void __launch_bounds__(256, 2) gemm_kernel(
    const float* __restrict__ x,
    const float* __restrict__ mask,
    const float* __restrict__ A,
    const float* __restrict__ bias,
    float* __restrict__ out)
{
    extern __shared__ __align__(16) char sm[];
    const u32 sbase = smem_u32(sm);
    const int t = threadIdx.x;
    const int wid = t >> 5;
    const int lane = t & 31;

    // ---- A -> B smem (bf16 hi/lo), pair-interleaved [n][k], n = t ----
    {
        const int n = t;
        const int c = n >> 1, s = n & 1;
        const float* Ac = A + (size_t)(s * 64) * 128 + c;
        char* rh = sm + OFF_BHI + n * XROW;
        char* rl = sm + OFF_BLO + n * XROW;
        #pragma unroll
        for (int kq = 0; kq < 8; kq++) {
            u32 hw[4], lw[4];
            #pragma unroll
            for (int e = 0; e < 4; e++) {
                float a0 = Ac[(kq * 8 + 2 * e) * 128];
                float a1 = Ac[(kq * 8 + 2 * e + 1) * 128];
                __nv_bfloat16 h0 = __float2bfloat16_rn(a0);
                __nv_bfloat16 h1 = __float2bfloat16_rn(a1);
                __nv_bfloat16 l0 = __float2bfloat16_rn(a0 - __bfloat162float(h0));
                __nv_bfloat16 l1 = __float2bfloat16_rn(a1 - __bfloat162float(h1));
                hw[e] = ((u32)__bfloat16_as_ushort(h1) << 16) | __bfloat16_as_ushort(h0);
                lw[e] = ((u32)__bfloat16_as_ushort(l1) << 16) | __bfloat16_as_ushort(l0);
            }
            *(uint4*)(rh + kq * 16) = make_uint4(hw[0], hw[1], hw[2], hw[3]);
            *(uint4*)(rl + kq * 16) = make_uint4(lw[0], lw[1], lw[2], lw[3]);
        }
    }

    // per-thread constants
    const int m0 = (wid & 1) * 32;       // 2 m-warps x 32 rows
    const int n0 = (wid >> 1) * 64;      // 4 n-warps x 64 B-rows (= 32 out cols)
    const int g = lane >> 3, ri = lane & 7;
    const u32 arow = (u32)(ri + ((g & 1) << 3));
    const u32 acol = (u32)((g >> 1) << 4);
    const u32 brow = (u32)(ri + ((g >> 1) << 3));
    const u32 bcol = (u32)((g & 1) << 4);
    const u32 XhiB = sbase + OFF_XHI + (m0 + arow) * XROW + acol;
    const u32 XloB = XhiB + (u32)(OFF_XLO - OFF_XHI);
    const u32 BhiB = sbase + OFF_BHI + (n0 + brow) * XROW + bcol;
    const u32 BloB = BhiB + (u32)(OFF_BLO - OFF_BHI);
    const float* A2p = A + 128 * 128;

    #pragma unroll
    for (int tile = 0; tile < 2; tile++) {
        const int row0 = (blockIdx.x * 2 + tile) * 64;

        // ---- X -> bf16 hi/lo (no c1 — independent of coef) ----
        {
            int row = t >> 2;                   // 0..63
            int cs  = (t & 3) * 16;             // 16 k-values
            const float* xr = x + (size_t)(row0 + row) * NF + cs;
            u32 hw[8], lw[8];
            #pragma unroll
            for (int qq = 0; qq < 4; qq++) {
                float4 v = *(const float4*)(xr + qq * 4);
                float vs[4] = {v.x, v.y, v.z, v.w};
                #pragma unroll
                for (int h2 = 0; h2 < 2; h2++) {
                    float va = vs[h2 * 2], vb = vs[h2 * 2 + 1];
                    __nv_bfloat16 ha = __float2bfloat16_rn(va);
                    __nv_bfloat16 hb = __float2bfloat16_rn(vb);
                    __nv_bfloat16 la = __float2bfloat16_rn(va - __bfloat162float(ha));
                    __nv_bfloat16 lb = __float2bfloat16_rn(vb - __bfloat162float(hb));
                    hw[qq * 2 + h2] = ((u32)__bfloat16_as_ushort(hb) << 16) | __bfloat16_as_ushort(ha);
                    lw[qq * 2 + h2] = ((u32)__bfloat16_as_ushort(lb) << 16) | __bfloat16_as_ushort(la);
                }
            }
            char* ph = sm + OFF_XHI + row * XROW + cs * 2;
            char* pl = sm + OFF_XLO + row * XROW + cs * 2;
            *(uint4*)(ph)      = make_uint4(hw[0], hw[1], hw[2], hw[3]);
            *(uint4*)(ph + 16) = make_uint4(hw[4], hw[5], hw[6], hw[7]);
            *(uint4*)(pl)      = make_uint4(lw[0], lw[1], lw[2], lw[3]);
            *(uint4*)(pl + 16) = make_uint4(lw[4], lw[5], lw[6], lw[7]);
        }
        __syncthreads();

        // ---- mainloop: K=64 -> 4 kb steps ----
        float acc[2][8][4];
        #pragma unroll
        for (int mt = 0; mt < 2; mt++)
            #pragma unroll
            for (int nb = 0; nb < 8; nb++)
                #pragma unroll
                for (int e = 0; e < 4; e++)
                    acc[mt][nb][e] = 0.f;

        #pragma unroll
        for (int kb = 0; kb < 4; kb++) {
            const u32 koff = kb * 32;              // 16 k-elements = 32 bytes
            u32 ah[2][4], al[2][4];
            LDSM_X4(ah[0][0], ah[0][1], ah[0][2], ah[0][3], XhiB + koff);
            LDSM_X4(ah[1][0], ah[1][1], ah[1][2], ah[1][3], XhiB + 16 * XROW + koff);
            LDSM_X4(al[0][0], al[0][1], al[0][2], al[0][3], XloB + koff);
            LDSM_X4(al[1][0], al[1][1], al[1][2], al[1][3], XloB + 16 * XROW + koff);

            u32 bh[8][2], bl[8][2];
            LDSM_X4(bh[0][0], bh[0][1], bh[1][0], bh[1][1], BhiB + koff);
            LDSM_X4(bh[2][0], bh[2][1], bh[3][0], bh[3][1], BhiB + 16 * XROW + koff);
            LDSM_X4(bh[4][0], bh[4][1], bh[5][0], bh[5][1], BhiB + 32 * XROW + koff);
            LDSM_X4(bh[6][0], bh[6][1], bh[7][0], bh[7][1], BhiB + 48 * XROW + koff);
            LDSM_X4(bl[0][0], bl[0][1], bl[1][0], bl[1][1], BloB + koff);
            LDSM_X4(bl[2][0], bl[2][1], bl[3][0], bl[3][1], BloB + 16 * XROW + koff);
            LDSM_X4(bl[4][0], bl[4][1], bl[5][0], bl[5][1], BloB + 32 * XROW + koff);
            LDSM_X4(bl[6][0], bl[6][1], bl[7][0], bl[7][1], BloB + 48 * XROW + koff);

            #pragma unroll
            for (int nb = 0; nb < 8; nb++) {
                #pragma unroll
                for (int mt = 0; mt < 2; mt++) {
                    mma16816(acc[mt][nb], ah[mt], bh[nb]);   // xhi * Bhi
                    mma16816(acc[mt][nb], al[mt], bh[nb]);   // xlo * Bhi
                    mma16816(acc[mt][nb], ah[mt], bl[nb]);   // xhi * Blo
                }
            }
        }

        // ---- wait for coef (first tile only; grid-global once satisfied) ----
        if (tile == 0) cudaGridDependencySynchronize();

        // ---- epilogue: out = (G0 + c1*G1 + c2*A2 + bias) * m ----
        #pragma unroll
        for (int mt = 0; mt < 2; mt++) {
            const int r1 = m0 + mt * 16 + (lane >> 2);
            const int r2 = r1 + 8;
            const int gr1 = row0 + r1, gr2 = row0 + r2;
            const float m1 = mask[gr1], m2 = mask[gr2];
            const float c11 = c1v_g[gr1], c12 = c1v_g[gr2];
            const float c21 = c2v_g[gr1], c22 = c2v_g[gr2];
            #pragma unroll
            for (int nb = 0; nb < 8; nb++) {
                const int cc = (n0 >> 1) + nb * 4 + (lane & 3);
                const float a2 = A2p[cc], bb = bias[cc];
                const float* d = acc[mt][nb];
                out[(size_t)gr1 * NO + cc] = (fmaf(c11, d[1], d[0]) + fmaf(c21, a2, bb)) * m1;
                out[(size_t)gr2 * NO + cc] = (fmaf(c12, d[3], d[2]) + fmaf(c22, a2, bb)) * m2;
            }
        }
        __syncthreads();   // X smem rewrite protection for next tile
    }
}

extern "C" void kernel_launch(void* const* d_in, const int* in_sizes, int n_in,
                              void* d_out, int out_size) {
    const float* x    = (const float*)d_in[0];
    const float* mask = (const float*)d_in[1];
    const float* A    = (const float*)d_in[2];
    const float* bias = (const float*)d_in[3];
    float* out = (float*)d_out;

    cudaFuncSetAttribute(gemm_kernel, cudaFuncAttributeMaxDynamicSharedMemorySize, GSMEM_TOTAL);

    coef_kernel<<<NB * 8, 512>>>(x, mask);

    cudaLaunchConfig_t cfg = {};
    cfg.gridDim = dim3((NB * NN) / 128, 1, 1);
    cfg.blockDim = dim3(256, 1, 1);
    cfg.dynamicSmemBytes = GSMEM_TOTAL;
    cfg.stream = 0;
    cudaLaunchAttribute at[1];
    at[0].id = cudaLaunchAttributeProgrammaticStreamSerialization;
    at[0].val.programmaticStreamSerializationAllowed = 1;
    cfg.attrs = at;
    cfg.numAttrs = 1;
    cudaLaunchKernelEx(&cfg, gemm_kernel, x, mask, A, bias, out);
}

// round 17
// speedup vs baseline: 1.0520x; 1.0520x over previous
#include <cuda_runtime.h>
#include <cuda_bf16.h>
#include <cstdint>
#include <cstddef>

#define NB 32
#define NN 1024
#define NF 64
#define NO 128

typedef unsigned long long u64;
typedef uint32_t u32;

#define KC (-14.4269504089f)                 // -10 * log2(e)
#define INV_KC (-0.0693147181f)              // 1 / KC

// Device scratch: coefficients from pairwise stage
__device__ float c1v_g[NB * NN];
__device__ float c2v_g[NB * NN];

// A as bf16 hi/lo, pair-interleaved [n][k]: n=2c+s -> A[(s*64+k)*128 + c], k<64
__device__ __align__(16) __nv_bfloat16 Bhi_g[256 * 64];
__device__ __align__(16) __nv_bfloat16 Blo_g[256 * 64];

__device__ __forceinline__ u32 smem_u32(const void* p) {
    u32 a;
    asm("{ .reg .u64 t; cvta.to.shared.u64 t, %1; cvt.u32.u64 %0, t; }" : "=r"(a) : "l"(p));
    return a;
}
__device__ __forceinline__ float fast_exp2(float t) {
    float r; asm("ex2.approx.f32 %0, %1;" : "=f"(r) : "f"(t)); return r;
}
__device__ __forceinline__ u64 pk2f(float lo, float hi) {
    u64 r; asm("mov.b64 %0, {%1, %2};" : "=l"(r) : "f"(lo), "f"(hi)); return r;
}
__device__ __forceinline__ void up2f(u64 v, float& a, float& b) {
    asm("mov.b64 {%0, %1}, %2;" : "=f"(a), "=f"(b) : "l"(v));
}
#define ADD2(d, a, b)   asm("add.rn.f32x2 %0, %1, %2;" : "=l"(d) : "l"(a), "l"(b))
#define FMA2IO(d, a, b) asm("fma.rn.f32x2 %0, %1, %2, %0;" : "+l"(d) : "l"(a), "l"(b))
#define ADD2ACC(d, a)   asm("add.rn.f32x2 %0, %1, %0;" : "+l"(d) : "l"(a))

#define LDSM_X4(r0, r1, r2, r3, addr) \
    asm volatile("ldmatrix.sync.aligned.m8n8.x4.shared.b16 {%0,%1,%2,%3}, [%4];" \
                 : "=r"(r0), "=r"(r1), "=r"(r2), "=r"(r3) : "r"(addr))

__device__ __forceinline__ void mma16816(float* d, const u32* a, const u32* b) {
    asm volatile(
        "mma.sync.aligned.m16n8k16.row.col.f32.bf16.bf16.f32 "
        "{%0,%1,%2,%3}, {%4,%5,%6,%7}, {%8,%9}, {%0,%1,%2,%3};"
        : "+f"(d[0]), "+f"(d[1]), "+f"(d[2]), "+f"(d[3])
        : "r"(a[0]), "r"(a[1]), "r"(a[2]), "r"(a[3]), "r"(b[0]), "r"(b[1]));
}

// ---------------------------------------------------------------------------
// Kernel 1: pairwise coefficients (+ A-conversion in the first 16 CTAs,
// pair-interleaved layout). grid = 256 (8/batch), 512 threads.
// 128 j's per CTA; q = t>>7 warp-uniform (broadcast smem loads), jl = t&127.
// ---------------------------------------------------------------------------
__global__ void __launch_bounds__(512) coef_kernel(
    const float* __restrict__ x, const float* __restrict__ mask,
    const float* __restrict__ A)
{
    __shared__ __align__(16) float xs[NN];
    __shared__ __align__(16) float ys[NN];
    __shared__ __align__(16) float kz[NN];
    __shared__ float redw[4][128];
    __shared__ float redd[4][128];

    const int b = blockIdx.x >> 3;
    const int jbase = (blockIdx.x & 7) * 128;
    const int t = threadIdx.x;

    // A -> Bhi/Blo (pair-interleaved): blocks 0..15, 1024 entries each
    if (blockIdx.x < 16) {
        #pragma unroll
        for (int p = 0; p < 2; p++) {
            int idx = blockIdx.x * 1024 + p * 512 + t;   // 0..16383
            int n = idx >> 6, k = idx & 63;
            float a = A[(size_t)(((n & 1) * 64 + k)) * 128 + (n >> 1)];
            __nv_bfloat16 h = __float2bfloat16_rn(a);
            Bhi_g[idx] = h;
            Blo_g[idx] = __float2bfloat16_rn(a - __bfloat162float(h));
        }
    }

    for (int i = t; i < NN; i += 512) {
        float2 c = *(const float2*)(x + ((size_t)b * NN + i) * NF + (NF - 2));
        xs[i] = c.x;
        ys[i] = c.y;
        kz[i] = KC * fmaf(c.y, c.y, c.x * c.x);
    }
    __syncthreads();

    const int q  = t >> 7;        // i-quarter, uniform within each warp
    const int jl = t & 127;
    const int j  = jbase + jl;
    const float Km2jx = -2.0f * KC * xs[j];
    const float Km2jy = -2.0f * KC * ys[j];
    const float Krj = kz[j];

    const u64 Kx2 = pk2f(Km2jx, Km2jx);
    const u64 Ky2 = pk2f(Km2jy, Km2jy);
    const u64 Kr2 = pk2f(Krj, Krj);

    const ulonglong2* X2 = (const ulonglong2*)(xs) + q * 64;
    const ulonglong2* Y2 = (const ulonglong2*)(ys) + q * 64;
    const ulonglong2* Z2 = (const ulonglong2*)(kz) + q * 64;

    u64 S1A = 0ULL, S2A = 0ULL, S1B = 0ULL, S2B = 0ULL;
    #pragma unroll 4
    for (int i = 0; i < 64; i++) {          // 4 points per iteration, broadcast loads
        ulonglong2 X = X2[i];
        ulonglong2 Y = Y2[i];
        ulonglong2 Z = Z2[i];

        u64 u0; ADD2(u0, Z.x, Kr2);
        FMA2IO(u0, Y.x, Ky2);
        FMA2IO(u0, X.x, Kx2);
        float ua, ub; up2f(u0, ua, ub);
        u64 e0 = pk2f(fast_exp2(ua), fast_exp2(ub));
        ADD2ACC(S1A, e0);
        FMA2IO(S2A, u0, e0);

        u64 u1; ADD2(u1, Z.y, Kr2);
        FMA2IO(u1, Y.y, Ky2);
        FMA2IO(u1, X.y, Kx2);
        float uc, ud; up2f(u1, uc, ud);
        u64 e1 = pk2f(fast_exp2(uc), fast_exp2(ud));
        ADD2ACC(S1B, e1);
        FMA2IO(S2B, u1, e1);
    }

    float a, bb, c, d;
    up2f(S1A, a, bb); up2f(S1B, c, d);
    float s1 = (a + bb) + (c + d);
    up2f(S2A, a, bb); up2f(S2B, c, d);
    float s2 = (a + bb) + (c + d);

    redw[q][jl] = s1;
    redd[q][jl] = s2;
    __syncthreads();

    if (t < 128) {
        float ws = (redw[0][t] + redw[1][t]) + (redw[2][t] + redw[3][t]);
        float dw = (redd[0][t] + redd[1][t]) + (redd[2][t] + redd[3][t]);
        int gj = b * NN + jbase + t;
        float m = mask[gj];
        c1v_g[gj] = fmaf(ws, m, -1.0f);
        c2v_g[gj] = (dw * INV_KC) * m;
    }
}

// ---------------------------------------------------------------------------
// Kernel 2: GEMM, pair-interleaved B (K=64, N=256 B-rows = 128 out cols).
//   Thread's mma col pair = (G0[c], G1[c]); epilogue applies c1 in fp32:
//   out = (G0 + c1*G1 + c2*A2 + bias) * m.
// grid = 256 (2 x 64-row tiles per CTA), 256 threads (8 warps),
// warp tile 32 rows x 64 B-rows. smem 92.2KB -> 2 CTAs/SM.
// Mainloop: 12 LDSM + 48 MMA per kb (4:1 MMA:LDSM).
// ---------------------------------------------------------------------------
#define XROW 144
#define OFF_XHI 0
#define OFF_XLO (64 * XROW)                  // 9216
#define OFF_BHI (2 * 64 * XROW)              // 18432
#define OFF_BLO (OFF_BHI + 256 * XROW)       // 55296
#define GSMEM_TOTAL (OFF_BLO + 256 * XROW)   // 92160

__global__ void __launch_bounds__(256, 2) gemm_kernel(
    const float* __restrict__ x,
    const float* __restrict__ mask,
    const float* __restrict__ A,
    const float* __restrict__ bias,
    float* __restrict__ out)
{
    extern __shared__ __align__(16) char sm[];
    const u32 sbase = smem_u32(sm);
    const int t = threadIdx.x;
    const int wid = t >> 5;
    const int lane = t & 31;

    // ---- B tiles: bf16 globals -> padded smem rows (once per CTA) ----
    {
        const uint4* bh = (const uint4*)Bhi_g;
        const uint4* bl = (const uint4*)Blo_g;
        #pragma unroll
        for (int pass = 0; pass < 8; pass++) {
            int idx = pass * 256 + t;           // 0..2047: 256 rows x 8 chunks
            int row = idx >> 3, chunk = idx & 7;
            char* dst = sm + row * XROW + chunk * 16;
            *(uint4*)(dst + OFF_BHI) = bh[idx];
            *(uint4*)(dst + OFF_BLO) = bl[idx];
        }
    }

    // per-thread constants
    const int m0 = (wid & 1) * 32;       // 2 m-warps x 32 rows
    const int n0 = (wid >> 1) * 64;      // 4 n-warps x 64 B-rows (= 32 out cols)
    const int g = lane >> 3, ri = lane & 7;
    const u32 arow = (u32)(ri + ((g & 1) << 3));
    const u32 acol = (u32)((g >> 1) << 4);
    const u32 brow = (u32)(ri + ((g >> 1) << 3));
    const u32 bcol = (u32)((g & 1) << 4);
    const u32 XhiB = sbase + OFF_XHI + (m0 + arow) * XROW + acol;
    const u32 XloB = XhiB + (u32)(OFF_XLO - OFF_XHI);
    const u32 BhiB = sbase + OFF_BHI + (n0 + brow) * XROW + bcol;
    const u32 BloB = BhiB + (u32)(OFF_BLO - OFF_BHI);
    const float* A2p = A + 128 * 128;

    #pragma unroll
    for (int tile = 0; tile < 2; tile++) {
        const int row0 = (blockIdx.x * 2 + tile) * 64;

        // ---- X -> bf16 hi/lo ----
        {
            int row = t >> 2;                   // 0..63
            int cs  = (t & 3) * 16;             // 16 k-values
            const float* xr = x + (size_t)(row0 + row) * NF + cs;
            u32 hw[8], lw[8];
            #pragma unroll
            for (int qq = 0; qq < 4; qq++) {
                float4 v = *(const float4*)(xr + qq * 4);
                float vs[4] = {v.x, v.y, v.z, v.w};
                #pragma unroll
                for (int h2 = 0; h2 < 2; h2++) {
                    float va = vs[h2 * 2], vb = vs[h2 * 2 + 1];
                    __nv_bfloat16 ha = __float2bfloat16_rn(va);
                    __nv_bfloat16 hb = __float2bfloat16_rn(vb);
                    __nv_bfloat16 la = __float2bfloat16_rn(va - __bfloat162float(ha));
                    __nv_bfloat16 lb = __float2bfloat16_rn(vb - __bfloat162float(hb));
                    hw[qq * 2 + h2] = ((u32)__bfloat16_as_ushort(hb) << 16) | __bfloat16_as_ushort(ha);
                    lw[qq * 2 + h2] = ((u32)__bfloat16_as_ushort(lb) << 16) | __bfloat16_as_ushort(la);
                }
            }
            char* ph = sm + OFF_XHI + row * XROW + cs * 2;
            char* pl = sm + OFF_XLO + row * XROW + cs * 2;
            *(uint4*)(ph)      = make_uint4(hw[0], hw[1], hw[2], hw[3]);
            *(uint4*)(ph + 16) = make_uint4(hw[4], hw[5], hw[6], hw[7]);
            *(uint4*)(pl)      = make_uint4(lw[0], lw[1], lw[2], lw[3]);
            *(uint4*)(pl + 16) = make_uint4(lw[4], lw[5], lw[6], lw[7]);
        }
        __syncthreads();

        // ---- mainloop: K=64 -> 4 kb steps ----
        float acc[2][8][4];
        #pragma unroll
        for (int mt = 0; mt < 2; mt++)
            #pragma unroll
            for (int nb = 0; nb < 8; nb++)
                #pragma unroll
                for (int e = 0; e < 4; e++)
                    acc[mt][nb][e] = 0.f;

        #pragma unroll
        for (int kb = 0; kb < 4; kb++) {
            const u32 koff = kb * 32;              // 16 k-elements = 32 bytes
            u32 ah[2][4], al[2][4];
            LDSM_X4(ah[0][0], ah[0][1], ah[0][2], ah[0][3], XhiB + koff);
            LDSM_X4(ah[1][0], ah[1][1], ah[1][2], ah[1][3], XhiB + 16 * XROW + koff);
            LDSM_X4(al[0][0], al[0][1], al[0][2], al[0][3], XloB + koff);
            LDSM_X4(al[1][0], al[1][1], al[1][2], al[1][3], XloB + 16 * XROW + koff);

            u32 bh[8][2], bl[8][2];
            LDSM_X4(bh[0][0], bh[0][1], bh[1][0], bh[1][1], BhiB + koff);
            LDSM_X4(bh[2][0], bh[2][1], bh[3][0], bh[3][1], BhiB + 16 * XROW + koff);
            LDSM_X4(bh[4][0], bh[4][1], bh[5][0], bh[5][1], BhiB + 32 * XROW + koff);
            LDSM_X4(bh[6][0], bh[6][1], bh[7][0], bh[7][1], BhiB + 48 * XROW + koff);
            LDSM_X4(bl[0][0], bl[0][1], bl[1][0], bl[1][1], BloB + koff);
            LDSM_X4(bl[2][0], bl[2][1], bl[3][0], bl[3][1], BloB + 16 * XROW + koff);
            LDSM_X4(bl[4][0], bl[4][1], bl[5][0], bl[5][1], BloB + 32 * XROW + koff);
            LDSM_X4(bl[6][0], bl[6][1], bl[7][0], bl[7][1], BloB + 48 * XROW + koff);

            #pragma unroll
            for (int nb = 0; nb < 8; nb++) {
                #pragma unroll
                for (int mt = 0; mt < 2; mt++) {
                    mma16816(acc[mt][nb], ah[mt], bh[nb]);   // xhi * Bhi
                    mma16816(acc[mt][nb], al[mt], bh[nb]);   // xlo * Bhi
                    mma16816(acc[mt][nb], ah[mt], bl[nb]);   // xhi * Blo
                }
            }
        }

        // ---- epilogue: out = (G0 + c1*G1 + c2*A2 + bias) * m ----
        #pragma unroll
        for (int mt = 0; mt < 2; mt++) {
            const int r1 = m0 + mt * 16 + (lane >> 2);
            const int r2 = r1 + 8;
            const int gr1 = row0 + r1, gr2 = row0 + r2;
            const float m1 = mask[gr1], m2 = mask[gr2];
            const float c11 = c1v_g[gr1], c12 = c1v_g[gr2];
            const float c21 = c2v_g[gr1], c22 = c2v_g[gr2];
            #pragma unroll
            for (int nb = 0; nb < 8; nb++) {
                const int cc = (n0 >> 1) + nb * 4 + (lane & 3);
                const float a2 = A2p[cc], bb = bias[cc];
                const float* d = acc[mt][nb];
                out[(size_t)gr1 * NO + cc] = (fmaf(c11, d[1], d[0]) + fmaf(c21, a2, bb)) * m1;
                out[(size_t)gr2 * NO + cc] = (fmaf(c12, d[3], d[2]) + fmaf(c22, a2, bb)) * m2;
            }
        }
        __syncthreads();   // X smem rewrite protection for next tile
    }
}

extern "C" void kernel_launch(void* const* d_in, const int* in_sizes, int n_in,
                              void* d_out, int out_size) {
    const float* x    = (const float*)d_in[0];
    const float* mask = (const float*)d_in[1];
    const float* A    = (const float*)d_in[2];
    const float* bias = (const float*)d_in[3];
    float* out = (float*)d_out;

    cudaFuncSetAttribute(gemm_kernel, cudaFuncAttributeMaxDynamicSharedMemorySize, GSMEM_TOTAL);

    coef_kernel<<<NB * 8, 512>>>(x, mask, A);
    gemm_kernel<<<(NB * NN) / 128, 256, GSMEM_TOTAL>>>(x, mask, A, bias, out);
}